// round 3
// baseline (speedup 1.0000x reference)
#include <cuda_runtime.h>
#include <math.h>

// Problem shape (fixed by the dataset): B=2, N=512, R=4
#define Bb 2
#define Nn 512
#define Rr 4
#define BR (Bb * Rr)

typedef unsigned long long ull;

// Scratch: masked sigmoid probabilities, per (b,r) matrix [BR][N][N]
__device__ float  g_rel[BR * Nn * Nn];
__device__ double g_lin;
__device__ double g_abs;

// ---------------------------------------------------------------------------
// Packed f32x2 helpers (sm_100+): one instruction operates on 2 floats.
// ---------------------------------------------------------------------------
__device__ __forceinline__ ull ffma2(ull a, ull b, ull c) {
    ull d;
    asm("fma.rn.f32x2 %0, %1, %2, %3;" : "=l"(d) : "l"(a), "l"(b), "l"(c));
    return d;
}
__device__ __forceinline__ ull fadd2(ull a, ull b) {
    ull d;
    asm("add.rn.f32x2 %0, %1, %2;" : "=l"(d) : "l"(a), "l"(b));
    return d;
}

// ---------------------------------------------------------------------------
// prep: rel[(b*R+r)][a][c] = sigmoid(logits[b][a][c][r]) * m[b][a] * m[b][c]
// Also zeroes the global accumulators (stream-ordered before the reducers).
// ---------------------------------------------------------------------------
__global__ void prep_kernel(const float* __restrict__ logits,
                            const int*   __restrict__ masks) {
    int idx = blockIdx.x * blockDim.x + threadIdx.x;   // over B*N*N
    if (idx == 0) { g_lin = 0.0; g_abs = 0.0; }
    if (idx >= Bb * Nn * Nn) return;
    int b   = idx / (Nn * Nn);
    int rem = idx - b * (Nn * Nn);
    int a   = rem / Nn;
    int c   = rem - a * Nn;

    float4 lg = reinterpret_cast<const float4*>(logits)[idx];
    float mm = (masks[b * Nn + a] > 0 && masks[b * Nn + c] > 0) ? 1.0f : 0.0f;

    float p0 = mm / (1.0f + __expf(-lg.x));
    float p1 = mm / (1.0f + __expf(-lg.y));
    float p2 = mm / (1.0f + __expf(-lg.z));
    float p3 = mm / (1.0f + __expf(-lg.w));

    int base = a * Nn + c;
    g_rel[((b * Rr + 0) * Nn * Nn) + base] = p0;
    g_rel[((b * Rr + 1) * Nn * Nn) + base] = p1;
    g_rel[((b * Rr + 2) * Nn * Nn) + base] = p2;
    g_rel[((b * Rr + 3) * Nn * Nn) + base] = p3;
}

// ---------------------------------------------------------------------------
// Linear term (exact, O(N^2)):  S_lin = sum_br sum_c [ N*s_c - s_c^2 ]
// ---------------------------------------------------------------------------
__global__ void colsum_kernel() {
    int br = blockIdx.x >> 2;
    int c  = ((blockIdx.x & 3) << 7) + threadIdx.x;
    const float* __restrict__ M = g_rel + br * Nn * Nn;
    float s = 0.0f;
    #pragma unroll 8
    for (int a = 0; a < Nn; ++a) s += M[a * Nn + c];
    double v = (double)s * (double)(Nn - (double)s);
    atomicAdd(&g_lin, v);
}

// ---------------------------------------------------------------------------
// Cube kernel: S_abs = sum_{br,a,b,c} | M[a][b] - M[a][c]*M[b][c] |
//
// Block = (br, 64a x 32b) tile, 128 threads (16 ty x 8 tx), thread tile 4x4.
// c processed in PAIRS with packed f32x2 math:
//   t2  = ffma2(pa2, pb2, -m2)          (1 FFMA2 / 2 elems, fma pipe)
//   t2 &= 0x7FFFFFFF7FFFFFFF            (2 LOP3  / 2 elems, alu pipe)
//   acc2 = fadd2(acc2, t2)              (1 FADD2 / 2 elems, fma pipe)
// Shared tiles use XOR swizzle phys_col = c ^ (2*(row>>2)) so the per-c-pair
// LDS.64 column reads are bank-conflict-free, and (c, c+1) stay contiguous.
// Grid 16x8x8 = 1024 blocks, 8 resident/SM -> single balanced wave.
// ---------------------------------------------------------------------------
#define TA 64
#define TB 32
#define CK 64

__global__ void __launch_bounds__(128, 8) cube_kernel() {
    __shared__ __align__(16) float tA[TA][CK];
    __shared__ __align__(16) float tB[TB][CK];
    __shared__ float wsum[4];

    const float* __restrict__ M = g_rel + blockIdx.z * (Nn * Nn);
    const int b0 = blockIdx.x * TB;
    const int a0 = blockIdx.y * TA;
    const int tid = threadIdx.x;
    const int tx = tid & 7;        // b direction (8)
    const int ty = tid >> 3;       // a direction (16)
    const int ay = ty * 4;
    const int bx = tx * 4;
    const int sA = 2 * ty;         // swizzle offsets (constant per thread)
    const int sB = 2 * tx;

    // Per-thread 4x4 of -M, each value duplicated into a f32x2 pair.
    ull mn[4][4];
    #pragma unroll
    for (int i = 0; i < 4; ++i) {
        float4 v = *reinterpret_cast<const float4*>(&M[(a0 + ay + i) * Nn + b0 + bx]);
        ull u0 = (ull)__float_as_uint(-v.x);
        ull u1 = (ull)__float_as_uint(-v.y);
        ull u2 = (ull)__float_as_uint(-v.z);
        ull u3 = (ull)__float_as_uint(-v.w);
        mn[i][0] = u0 | (u0 << 32);
        mn[i][1] = u1 | (u1 << 32);
        mn[i][2] = u2 | (u2 << 32);
        mn[i][3] = u3 | (u3 << 32);
    }

    ull acc0 = 0, acc1 = 0;

    // Staging writer mappings (rows spread so STS.64 is near-conflict-free)
    const int arow = 4 * (tid & 15) + ((tid >> 4) & 3);  // 0..63
    const int acol = (tid >> 6) * 32;                     // {0, 32}
    const int asw  = 2 * ((arow >> 2) & 31);
    const int brow = 4 * (tid & 7) + ((tid >> 3) & 3);   // 0..31
    const int bcol = (tid >> 5) * 16;                     // {0,16,32,48}
    const int bsw  = 2 * (brow >> 2);

    for (int c0 = 0; c0 < Nn; c0 += CK) {
        __syncthreads();
        // Stage A rows [a0, a0+64) x c-chunk
        #pragma unroll
        for (int k = 0; k < 32; k += 4) {
            float4 v = *reinterpret_cast<const float4*>(&M[(a0 + arow) * Nn + c0 + acol + k]);
            *reinterpret_cast<float2*>(&tA[arow][(acol + k) ^ asw])     = make_float2(v.x, v.y);
            *reinterpret_cast<float2*>(&tA[arow][(acol + k + 2) ^ asw]) = make_float2(v.z, v.w);
        }
        // Stage B rows [b0, b0+32) x c-chunk
        #pragma unroll
        for (int k = 0; k < 16; k += 4) {
            float4 v = *reinterpret_cast<const float4*>(&M[(b0 + brow) * Nn + c0 + bcol + k]);
            *reinterpret_cast<float2*>(&tB[brow][(bcol + k) ^ bsw])     = make_float2(v.x, v.y);
            *reinterpret_cast<float2*>(&tB[brow][(bcol + k + 2) ^ bsw]) = make_float2(v.z, v.w);
        }
        __syncthreads();

        #pragma unroll 8
        for (int cc = 0; cc < CK; cc += 2) {
            ull pa[4], pb[4];
            const int oA = cc ^ sA;
            const int oB = cc ^ sB;
            #pragma unroll
            for (int i = 0; i < 4; ++i)
                pa[i] = *reinterpret_cast<const ull*>(&tA[ay + i][oA]);
            #pragma unroll
            for (int j = 0; j < 4; ++j)
                pb[j] = *reinterpret_cast<const ull*>(&tB[bx + j][oB]);

            #pragma unroll
            for (int i = 0; i < 4; ++i) {
                #pragma unroll
                for (int j = 0; j < 4; ++j) {
                    ull t = ffma2(pa[i], pb[j], mn[i][j]);
                    t &= 0x7FFFFFFF7FFFFFFFULL;            // packed |.| (alu pipe)
                    if ((j & 1) == 0) acc0 = fadd2(acc0, t);
                    else              acc1 = fadd2(acc1, t);
                }
            }
        }
    }

    // Reduce: unpack the two packed accumulators
    float tsum = __uint_as_float((unsigned)(acc0 & 0xFFFFFFFFu))
               + __uint_as_float((unsigned)(acc0 >> 32))
               + __uint_as_float((unsigned)(acc1 & 0xFFFFFFFFu))
               + __uint_as_float((unsigned)(acc1 >> 32));
    #pragma unroll
    for (int o = 16; o > 0; o >>= 1)
        tsum += __shfl_xor_sync(0xffffffffu, tsum, o);
    if ((tid & 31) == 0) wsum[tid >> 5] = tsum;
    __syncthreads();
    if (tid == 0) {
        float bsum = (wsum[0] + wsum[1]) + (wsum[2] + wsum[3]);
        atomicAdd(&g_abs, (double)bsum);
    }
}

// ---------------------------------------------------------------------------
// Finalize:  out = WEIGHT * 0.5*(S_lin + S_abs) / (R*B)
// ---------------------------------------------------------------------------
__global__ void fin_kernel(float* __restrict__ out, int n) {
    double v = 0.5 * (g_lin + g_abs) / (double)(Bb * Rr);
    for (int i = threadIdx.x; i < n; i += blockDim.x) out[i] = (float)v;
}

extern "C" void kernel_launch(void* const* d_in, const int* in_sizes, int n_in,
                              void* d_out, int out_size) {
    const float* logits = (const float*)d_in[0];   // [B, N, N, R] f32
    const int*   masks  = (const int*)d_in[1];     // [B, N] i32

    prep_kernel<<<(Bb * Nn * Nn + 255) / 256, 256>>>(logits, masks);
    colsum_kernel<<<BR * 4, 128>>>();
    dim3 grid(Nn / TB, Nn / TA, BR);   // 16 x 8 x 8 = 1024 blocks
    cube_kernel<<<grid, 128>>>();
    fin_kernel<<<1, 32>>>((float*)d_out, out_size);
}